// round 3
// baseline (speedup 1.0000x reference)
#include <cuda_runtime.h>

// PrototypeLoss: mean_i || features[i] - prototypes[labels[i]] ||^2
// N=131072, D=512, C=1000. features f32 [N,D], labels int32 OR int64 [N]
// (JAX x64-disabled downcasts int64->int32; detect at runtime), prototypes
// f32 [C,D]. Output: f32 [1,1].
//
// HBM-bound: 256MB features streamed once; prototypes (2MB) L2-resident.

#define N_SAMPLES 131072
#define DIM 512
#define NUM_CLASSES 1000

__device__ double g_acc;
__device__ int g_labels_are_i64;

// Detect label dtype: for int64 labels in [0,1000), all odd 32-bit words are
// zero. For int32 labels, odd words are labels of odd samples (all-zero has
// probability ~(1e-3)^256 ~ 0). Reads only the first 1024 int32 words, which
// is in-bounds under either interpretation (buffer >= N*4 bytes).
__global__ void proto_loss_init_kernel(const int* __restrict__ labels_as_i32) {
    g_acc = 0.0;
    int any_odd_nonzero = 0;
    #pragma unroll 8
    for (int i = 1; i < 1024; i += 2)
        any_odd_nonzero |= (labels_as_i32[i] != 0);
    g_labels_are_i64 = !any_odd_nonzero;
}

__global__ __launch_bounds__(256) void proto_loss_main_kernel(
    const float* __restrict__ feat,
    const void* __restrict__ labels,
    const float* __restrict__ protos)
{
    const int warp_global = (blockIdx.x * blockDim.x + threadIdx.x) >> 5;
    const int lane = threadIdx.x & 31;

    // Uniform branch: flag is identical for the whole grid.
    long long lab;
    if (g_labels_are_i64) {
        lab = ((const long long*)labels)[warp_global];
    } else {
        lab = (long long)((const int*)labels)[warp_global];
    }
    // Defensive clamp: never produce an OOB prototype index.
    if (lab < 0) lab = 0;
    if (lab >= NUM_CLASSES) lab = NUM_CLASSES - 1;

    const float4* __restrict__ f =
        reinterpret_cast<const float4*>(feat + (size_t)warp_global * DIM);
    const float4* __restrict__ p =
        reinterpret_cast<const float4*>(protos + (size_t)lab * DIM);

    // Front-batch all 8 wide loads (4 feature + 4 proto float4 per lane) so
    // the warp has maximal memory-level parallelism before any FMA executes.
    // 512 floats = 128 float4 per row; lane + 32*i interleave = fully
    // coalesced 512B warp transactions.
    float4 a0 = f[lane +  0];
    float4 a1 = f[lane + 32];
    float4 a2 = f[lane + 64];
    float4 a3 = f[lane + 96];
    float4 b0 = p[lane +  0];
    float4 b1 = p[lane + 32];
    float4 b2 = p[lane + 64];
    float4 b3 = p[lane + 96];

    float s = 0.0f;
    float d;
    d = a0.x - b0.x; s = fmaf(d, d, s);
    d = a0.y - b0.y; s = fmaf(d, d, s);
    d = a0.z - b0.z; s = fmaf(d, d, s);
    d = a0.w - b0.w; s = fmaf(d, d, s);
    d = a1.x - b1.x; s = fmaf(d, d, s);
    d = a1.y - b1.y; s = fmaf(d, d, s);
    d = a1.z - b1.z; s = fmaf(d, d, s);
    d = a1.w - b1.w; s = fmaf(d, d, s);
    d = a2.x - b2.x; s = fmaf(d, d, s);
    d = a2.y - b2.y; s = fmaf(d, d, s);
    d = a2.z - b2.z; s = fmaf(d, d, s);
    d = a2.w - b2.w; s = fmaf(d, d, s);
    d = a3.x - b3.x; s = fmaf(d, d, s);
    d = a3.y - b3.y; s = fmaf(d, d, s);
    d = a3.z - b3.z; s = fmaf(d, d, s);
    d = a3.w - b3.w; s = fmaf(d, d, s);

    // Warp reduction
    #pragma unroll
    for (int o = 16; o > 0; o >>= 1)
        s += __shfl_xor_sync(0xffffffffu, s, o);

    __shared__ float warp_sums[8];
    const int wid = threadIdx.x >> 5;
    if (lane == 0) warp_sums[wid] = s;
    __syncthreads();

    if (threadIdx.x == 0) {
        float t = 0.0f;
        #pragma unroll
        for (int i = 0; i < 8; i++) t += warp_sums[i];
        atomicAdd(&g_acc, (double)t);
    }
}

__global__ void proto_loss_finalize_kernel(float* __restrict__ out) {
    out[0] = (float)(g_acc / (double)N_SAMPLES);
}

extern "C" void kernel_launch(void* const* d_in, const int* in_sizes, int n_in,
                              void* d_out, int out_size) {
    const float* feat   = (const float*)d_in[0];
    const void*  labels = d_in[1];
    const float* protos = (const float*)d_in[2];
    float* out = (float*)d_out;

    proto_loss_init_kernel<<<1, 1>>>((const int*)labels);

    // 1 warp per sample, 8 warps (256 threads) per block
    const int warps_per_block = 8;
    const int blocks = N_SAMPLES / warps_per_block;  // 16384
    proto_loss_main_kernel<<<blocks, warps_per_block * 32>>>(feat, labels, protos);

    proto_loss_finalize_kernel<<<1, 1>>>(out);
}

// round 6
// speedup vs baseline: 1.1714x; 1.1714x over previous
#include <cuda_runtime.h>

// PrototypeLoss: mean_i || features[i] - prototypes[labels[i]] ||^2
// N=131072, D=512, C=1000. features f32 [N,D], labels int32 OR int64 [N]
// (detected per-block at runtime), prototypes f32 [C,D]. Output f32 [1,1].
//
// Single fused kernel (R3 design, resubmitted after two infra timeouts):
// per-block dtype detect (L2-broadcast reads + __syncthreads_or), streaming
// squared-distance with 16 front-batched LDG.128 per warp (2 samples/warp),
// block reduce, one double atomicAdd per block, last-block finalize + reset
// (graph-replay safe).

#define N_SAMPLES 131072
#define DIM 512
#define NUM_CLASSES 1000
#define WARPS_PER_BLOCK 8
#define SAMPLES_PER_WARP 2
#define SAMPLES_PER_BLOCK (WARPS_PER_BLOCK * SAMPLES_PER_WARP)  // 16
#define NUM_BLOCKS (N_SAMPLES / SAMPLES_PER_BLOCK)              // 8192

__device__ double g_acc;            // zero at module load; reset by last block
__device__ unsigned int g_count;    // zero at module load; reset by last block

__device__ __forceinline__ float sample_dist2(
    const float4* __restrict__ f, const float4* __restrict__ p, int lane)
{
    // Front-batch 8 wide loads for max MLP; each is a coalesced 512B warp txn.
    float4 a0 = f[lane +  0];
    float4 a1 = f[lane + 32];
    float4 a2 = f[lane + 64];
    float4 a3 = f[lane + 96];
    float4 b0 = p[lane +  0];
    float4 b1 = p[lane + 32];
    float4 b2 = p[lane + 64];
    float4 b3 = p[lane + 96];
    float s = 0.0f, d;
    d = a0.x - b0.x; s = fmaf(d, d, s);
    d = a0.y - b0.y; s = fmaf(d, d, s);
    d = a0.z - b0.z; s = fmaf(d, d, s);
    d = a0.w - b0.w; s = fmaf(d, d, s);
    d = a1.x - b1.x; s = fmaf(d, d, s);
    d = a1.y - b1.y; s = fmaf(d, d, s);
    d = a1.z - b1.z; s = fmaf(d, d, s);
    d = a1.w - b1.w; s = fmaf(d, d, s);
    d = a2.x - b2.x; s = fmaf(d, d, s);
    d = a2.y - b2.y; s = fmaf(d, d, s);
    d = a2.z - b2.z; s = fmaf(d, d, s);
    d = a2.w - b2.w; s = fmaf(d, d, s);
    d = a3.x - b3.x; s = fmaf(d, d, s);
    d = a3.y - b3.y; s = fmaf(d, d, s);
    d = a3.z - b3.z; s = fmaf(d, d, s);
    d = a3.w - b3.w; s = fmaf(d, d, s);
    return s;
}

__global__ __launch_bounds__(256) void proto_loss_fused_kernel(
    const float* __restrict__ feat,
    const void* __restrict__ labels,
    const float* __restrict__ protos,
    float* __restrict__ out)
{
    const int lane = threadIdx.x & 31;
    const int wid  = threadIdx.x >> 5;

    // ---- Label dtype detect (per block, uniform result) ----
    // Words 1,3,...,511 are: int64 hi-words (all 0, since labels < 1000) OR
    // int32 labels of samples 1..511 (P(all zero) ~ 1e-768). Same 2KB read by
    // every block -> L2 broadcast, effectively free.
    const int* li = (const int*)labels;
    int labels_are_i32 = __syncthreads_or(li[2 * threadIdx.x + 1] != 0);

    const int warp_global = blockIdx.x * WARPS_PER_BLOCK + wid;
    const int s0 = warp_global * SAMPLES_PER_WARP;
    const int s1 = s0 + 1;

    long long lab0, lab1;
    if (labels_are_i32) {
        lab0 = (long long)li[s0];
        lab1 = (long long)li[s1];
    } else {
        const long long* l64 = (const long long*)labels;
        lab0 = l64[s0];
        lab1 = l64[s1];
    }
    // Defensive clamp: never OOB into prototypes.
    lab0 = (lab0 < 0) ? 0 : (lab0 >= NUM_CLASSES ? NUM_CLASSES - 1 : lab0);
    lab1 = (lab1 < 0) ? 0 : (lab1 >= NUM_CLASSES ? NUM_CLASSES - 1 : lab1);

    const float4* f0 = (const float4*)(feat + (size_t)s0 * DIM);
    const float4* f1 = (const float4*)(feat + (size_t)s1 * DIM);
    const float4* p0 = (const float4*)(protos + (size_t)lab0 * DIM);
    const float4* p1 = (const float4*)(protos + (size_t)lab1 * DIM);

    float s = sample_dist2(f0, p0, lane) + sample_dist2(f1, p1, lane);

    // ---- Warp reduce ----
    #pragma unroll
    for (int o = 16; o > 0; o >>= 1)
        s += __shfl_xor_sync(0xffffffffu, s, o);

    // ---- Block reduce ----
    __shared__ float warp_sums[WARPS_PER_BLOCK];
    __shared__ bool is_last;
    if (lane == 0) warp_sums[wid] = s;
    __syncthreads();

    if (threadIdx.x == 0) {
        float t = 0.0f;
        #pragma unroll
        for (int i = 0; i < WARPS_PER_BLOCK; i++) t += warp_sums[i];
        atomicAdd(&g_acc, (double)t);
        __threadfence();
        unsigned int done = atomicAdd(&g_count, 1u);
        is_last = (done == (unsigned int)(gridDim.x - 1));
    }
    __syncthreads();

    // ---- Last-block finalize + reset (keeps graph replays correct) ----
    if (is_last && threadIdx.x == 0) {
        // All other blocks' g_acc additions are ordered before their g_count
        // increments (threadfence); seeing done==grid-1 makes them visible.
        double total = *((volatile double*)&g_acc);
        out[0] = (float)(total / (double)N_SAMPLES);
        g_acc = 0.0;
        g_count = 0u;
        __threadfence();
    }
}

extern "C" void kernel_launch(void* const* d_in, const int* in_sizes, int n_in,
                              void* d_out, int out_size) {
    const float* feat   = (const float*)d_in[0];
    const void*  labels = d_in[1];
    const float* protos = (const float*)d_in[2];
    float* out = (float*)d_out;

    proto_loss_fused_kernel<<<NUM_BLOCKS, WARPS_PER_BLOCK * 32>>>(
        feat, labels, protos, out);
}